// round 6
// baseline (speedup 1.0000x reference)
#include <cuda_runtime.h>
#include <cuda_bf16.h>
#include <mma.h>
#include <math.h>

using namespace nvcuda;

#define DH 128
#define NMAX 100000
#define EMAX 3200000
#define GMAX 512
#define SCAN_TILE 1024
#define NBMAX ((NMAX + SCAN_TILE - 1) / SCAN_TILE)   // 98

// Scratch (static device globals — no runtime allocation)
__device__ __align__(16) __nv_bfloat16 g_Xbf[NMAX * DH];   // bf16 copy of layer input
__device__ __align__(16) __nv_bfloat16 g_Abf[NMAX * DH];   // GEMM out * dinv[row]
__device__ __align__(16) __nv_bfloat16 g_Hbf[NMAX * DH];   // gather out (h1/h2)
__device__ __align__(16) __nv_bfloat16 g_W1bf[DH * DH];
__device__ __align__(16) __nv_bfloat16 g_W2bf[DH * DH];
__device__ float g_dinv[NMAX];
__device__ int   g_deg[NMAX];
__device__ int   g_rowptr[NMAX + 1];
__device__ int   g_cursor[NMAX];
__device__ int   g_src[EMAX];
__device__ int   g_bsum[NBMAX + 32];
__device__ int   g_boff[NBMAX + 32];
__device__ float g_pooled[GMAX * DH];
__device__ int   g_cnt[GMAX];

// ---------------- reset: deg=1 (self loop), pooled=0, cnt=0 ----------------
__global__ void k_reset(int n, int g) {
    int idx = blockIdx.x * blockDim.x + threadIdx.x;
    if (idx < n) g_deg[idx] = 1;
    if (idx < g * DH) g_pooled[idx] = 0.0f;
    if (idx < g) g_cnt[idx] = 0;
}

__global__ void k_deg_count(const int* __restrict__ col, int E) {
    int e = blockIdx.x * blockDim.x + threadIdx.x;
    if (e < E) atomicAdd(&g_deg[col[e]], 1);
}

__global__ void k_dinv(int n) {
    int i = blockIdx.x * blockDim.x + threadIdx.x;
    if (i < n) g_dinv[i] = rsqrtf((float)g_deg[i]);
}

// ---------------- fp32 -> bf16 converter ----------------
__global__ void k_cvt(const float* __restrict__ src, __nv_bfloat16* __restrict__ dst, int total4) {
    int i = blockIdx.x * blockDim.x + threadIdx.x;   // float4 index
    if (i >= total4) return;
    float4 v = __ldg(reinterpret_cast<const float4*>(src) + i);
    __nv_bfloat162 p0 = __floats2bfloat162_rn(v.x, v.y);
    __nv_bfloat162 p1 = __floats2bfloat162_rn(v.z, v.w);
    uint2 o;
    o.x = *reinterpret_cast<unsigned int*>(&p0);
    o.y = *reinterpret_cast<unsigned int*>(&p1);
    reinterpret_cast<uint2*>(dst)[i] = o;
}

// ---------------- 3-phase scan of (deg-1) -> rowptr, cursor ----------------
__global__ __launch_bounds__(256) void k_scanA(int n) {
    int base = blockIdx.x * SCAN_TILE;
    int tid = threadIdx.x;
    int s = 0;
    #pragma unroll
    for (int j = 0; j < 4; ++j) {
        int i = base + tid * 4 + j;
        if (i < n) s += g_deg[i] - 1;
    }
    #pragma unroll
    for (int o = 16; o; o >>= 1) s += __shfl_down_sync(~0u, s, o);
    __shared__ int ws[8];
    if ((tid & 31) == 0) ws[tid >> 5] = s;
    __syncthreads();
    if (tid < 8) {
        int v = ws[tid];
        #pragma unroll
        for (int o = 4; o; o >>= 1) v += __shfl_down_sync(0xff, v, o);
        if (tid == 0) g_bsum[blockIdx.x] = v;
    }
}

__global__ __launch_bounds__(128) void k_scanB(int nb, int n) {
    int tid = threadIdx.x;
    int s = (tid < nb) ? g_bsum[tid] : 0;
    int lane = tid & 31, wid = tid >> 5;
    int x = s;
    #pragma unroll
    for (int o = 1; o < 32; o <<= 1) {
        int y = __shfl_up_sync(~0u, x, o);
        if (lane >= o) x += y;
    }
    __shared__ int ws[4];
    if (lane == 31) ws[wid] = x;
    __syncthreads();
    if (tid < 4) {
        int y = ws[tid];
        #pragma unroll
        for (int o = 1; o < 4; o <<= 1) {
            int z = __shfl_up_sync(0xf, y, o);
            if (tid >= o) y += z;
        }
        ws[tid] = y;
    }
    __syncthreads();
    int incl = x + (wid ? ws[wid - 1] : 0);
    if (tid < nb) g_boff[tid] = incl - s;
    if (tid == 127) g_rowptr[n] = ws[3];
}

__global__ __launch_bounds__(256) void k_scanC(int n) {
    int base = blockIdx.x * SCAN_TILE;
    int tid = threadIdx.x;
    int lane = tid & 31, wid = tid >> 5;
    int v[4], s = 0;
    #pragma unroll
    for (int j = 0; j < 4; ++j) {
        int i = base + tid * 4 + j;
        v[j] = (i < n) ? g_deg[i] - 1 : 0;
        s += v[j];
    }
    int x = s;
    #pragma unroll
    for (int o = 1; o < 32; o <<= 1) {
        int y = __shfl_up_sync(~0u, x, o);
        if (lane >= o) x += y;
    }
    __shared__ int ws[8];
    if (lane == 31) ws[wid] = x;
    __syncthreads();
    if (tid < 8) {
        int y = ws[tid];
        #pragma unroll
        for (int o = 1; o < 8; o <<= 1) {
            int z = __shfl_up_sync(0xff, y, o);
            if (tid >= o) y += z;
        }
        ws[tid] = y;
    }
    __syncthreads();
    int excl = x - s + (wid ? ws[wid - 1] : 0) + g_boff[blockIdx.x];
    #pragma unroll
    for (int j = 0; j < 4; ++j) {
        int i = base + tid * 4 + j;
        if (i < n) {
            g_rowptr[i] = excl;
            g_cursor[i] = excl;
            excl += v[j];
        }
    }
}

// ---------------- fill CSR ----------------
__global__ void k_fill(const int* __restrict__ row, const int* __restrict__ col, int E) {
    int e = blockIdx.x * blockDim.x + threadIdx.x;
    if (e >= E) return;
    int r = __ldg(&row[e]);
    int c = __ldg(&col[e]);
    int pos = atomicAdd(&g_cursor[c], 1);
    g_src[pos] = r;
}

// ------- WMMA GEMM: Abf = bf16( (Xbf @ Wbf) * dinv[row] ), 64 rows/block -------
__global__ __launch_bounds__(256) void k_gemm(const __nv_bfloat16* __restrict__ X,
                                              const __nv_bfloat16* __restrict__ W,
                                              __nv_bfloat16* __restrict__ Y, int n) {
    extern __shared__ char smem[];
    __nv_bfloat16* Xs = reinterpret_cast<__nv_bfloat16*>(smem);             // 64*128 bf16 = 16 KB
    __nv_bfloat16* Ws = reinterpret_cast<__nv_bfloat16*>(smem + 16384);     // 128*128 bf16 = 32 KB
    float*         Os = reinterpret_cast<float*>(smem + 49152);             // 64*128 f32 = 32 KB

    int tid = threadIdx.x;
    int rowBase = blockIdx.x * 64;

    // load W (full) and X tile, uint4 = 8 bf16
    const uint4* Wg = reinterpret_cast<const uint4*>(W);
    uint4* Ws4 = reinterpret_cast<uint4*>(Ws);
    #pragma unroll
    for (int i = tid; i < DH * DH / 8; i += 256) Ws4[i] = Wg[i];

    const uint4* Xg = reinterpret_cast<const uint4*>(X);
    uint4* Xs4 = reinterpret_cast<uint4*>(Xs);
    #pragma unroll
    for (int i = tid; i < 64 * DH / 8; i += 256) {
        int r = i >> 4;                 // 16 uint4 per row
        int gr = rowBase + r;
        Xs4[i] = (gr < n) ? Xg[(size_t)gr * 16 + (i & 15)] : make_uint4(0, 0, 0, 0);
    }
    __syncthreads();

    // 8 warps: warp_row = w&3 (16-row block), warp_col = w>>2 (64-col block)
    int w = tid >> 5;
    int wr = (w & 3) * 16;
    int wc = (w >> 2) * 64;

    wmma::fragment<wmma::accumulator, 16, 16, 16, float> fc[4];
    #pragma unroll
    for (int j = 0; j < 4; ++j) wmma::fill_fragment(fc[j], 0.0f);

    #pragma unroll
    for (int k = 0; k < 8; ++k) {
        wmma::fragment<wmma::matrix_a, 16, 16, 16, __nv_bfloat16, wmma::row_major> fa;
        wmma::load_matrix_sync(fa, Xs + wr * DH + k * 16, DH);
        #pragma unroll
        for (int j = 0; j < 4; ++j) {
            wmma::fragment<wmma::matrix_b, 16, 16, 16, __nv_bfloat16, wmma::row_major> fb;
            wmma::load_matrix_sync(fb, Ws + (k * 16) * DH + wc + j * 16, DH);
            wmma::mma_sync(fc[j], fa, fb, fc[j]);
        }
    }
    #pragma unroll
    for (int j = 0; j < 4; ++j)
        wmma::store_matrix_sync(Os + wr * DH + wc + j * 16, fc[j], DH, wmma::mem_row_major);
    __syncthreads();

    // epilogue: scale by dinv[row], convert to bf16, store
    int r = tid >> 2;                 // 4 threads per row
    int cb = (tid & 3) * 32;          // 32 cols per thread
    int gr = rowBase + r;
    if (gr < n) {
        float s = __ldg(&g_dinv[gr]);
        #pragma unroll
        for (int j = 0; j < 8; ++j) {
            float4 v = *reinterpret_cast<float4*>(&Os[r * DH + cb + j * 4]);
            __nv_bfloat162 p0 = __floats2bfloat162_rn(v.x * s, v.y * s);
            __nv_bfloat162 p1 = __floats2bfloat162_rn(v.z * s, v.w * s);
            uint2 o;
            o.x = *reinterpret_cast<unsigned int*>(&p0);
            o.y = *reinterpret_cast<unsigned int*>(&p1);
            reinterpret_cast<uint2*>(Y)[(size_t)gr * 32 + ((cb >> 2) + j)] = o;
        }
    }
}

__device__ __forceinline__ void bf8_acc(float* acc, uint4 u) {
    __nv_bfloat162* p = reinterpret_cast<__nv_bfloat162*>(&u);
    #pragma unroll
    for (int i = 0; i < 4; ++i) {
        float2 f = __bfloat1622float2(p[i]);
        acc[2 * i] += f.x;
        acc[2 * i + 1] += f.y;
    }
}

// -------- fused gather: H[c,:] = bf16(relu( dinv[c]*(A'[c]+sum A'[r]) + b )) ---
// 16 lanes per node; lane owns 8 bf16 (16 B) of the 256 B row.
__global__ __launch_bounds__(256) void k_gather(const __nv_bfloat16* __restrict__ Ap,
                                                __nv_bfloat16* __restrict__ H,
                                                const float* __restrict__ bias,
                                                int n) {
    int sub = threadIdx.x & 15;
    int node = (blockIdx.x * blockDim.x + threadIdx.x) >> 4;
    if (node >= n) return;

    const uint4* A4 = reinterpret_cast<const uint4*>(Ap);   // 16 uint4 per row

    float acc[8] = {};
    bf8_acc(acc, __ldg(&A4[(size_t)node * 16 + sub]));      // self term

    int e = g_rowptr[node];
    int end = g_rowptr[node + 1];

    for (; e + 4 <= end; e += 4) {
        int r0 = __ldg(&g_src[e + 0]);
        int r1 = __ldg(&g_src[e + 1]);
        int r2 = __ldg(&g_src[e + 2]);
        int r3 = __ldg(&g_src[e + 3]);
        uint4 u0 = __ldg(&A4[(size_t)r0 * 16 + sub]);
        uint4 u1 = __ldg(&A4[(size_t)r1 * 16 + sub]);
        uint4 u2 = __ldg(&A4[(size_t)r2 * 16 + sub]);
        uint4 u3 = __ldg(&A4[(size_t)r3 * 16 + sub]);
        bf8_acc(acc, u0); bf8_acc(acc, u1); bf8_acc(acc, u2); bf8_acc(acc, u3);
    }
    for (; e < end; ++e) {
        int r = __ldg(&g_src[e]);
        bf8_acc(acc, __ldg(&A4[(size_t)r * 16 + sub]));
    }

    float dc = __ldg(&g_dinv[node]);
    float4 b0 = __ldg(reinterpret_cast<const float4*>(bias) + sub * 2);
    float4 b1 = __ldg(reinterpret_cast<const float4*>(bias) + sub * 2 + 1);
    float o[8];
    o[0] = fmaxf(fmaf(acc[0], dc, b0.x), 0.f);
    o[1] = fmaxf(fmaf(acc[1], dc, b0.y), 0.f);
    o[2] = fmaxf(fmaf(acc[2], dc, b0.z), 0.f);
    o[3] = fmaxf(fmaf(acc[3], dc, b0.w), 0.f);
    o[4] = fmaxf(fmaf(acc[4], dc, b1.x), 0.f);
    o[5] = fmaxf(fmaf(acc[5], dc, b1.y), 0.f);
    o[6] = fmaxf(fmaf(acc[6], dc, b1.z), 0.f);
    o[7] = fmaxf(fmaf(acc[7], dc, b1.w), 0.f);
    __nv_bfloat162 q0 = __floats2bfloat162_rn(o[0], o[1]);
    __nv_bfloat162 q1 = __floats2bfloat162_rn(o[2], o[3]);
    __nv_bfloat162 q2 = __floats2bfloat162_rn(o[4], o[5]);
    __nv_bfloat162 q3 = __floats2bfloat162_rn(o[6], o[7]);
    uint4 ou;
    ou.x = *reinterpret_cast<unsigned int*>(&q0);
    ou.y = *reinterpret_cast<unsigned int*>(&q1);
    ou.z = *reinterpret_cast<unsigned int*>(&q2);
    ou.w = *reinterpret_cast<unsigned int*>(&q3);
    reinterpret_cast<uint4*>(H)[(size_t)node * 16 + sub] = ou;
}

// ---------------- mean pool from bf16 H (fp32 atomics) ----------------
__global__ void k_pool(const __nv_bfloat16* __restrict__ H, const int* __restrict__ batch, int n) {
    int lane = threadIdx.x & 31;
    int node = (blockIdx.x * blockDim.x + threadIdx.x) >> 5;
    if (node >= n) return;
    int b = __ldg(&batch[node]);
    uint2 u = __ldg(reinterpret_cast<const uint2*>(H) + (size_t)node * 32 + lane);
    __nv_bfloat162 a = *reinterpret_cast<__nv_bfloat162*>(&u.x);
    __nv_bfloat162 c = *reinterpret_cast<__nv_bfloat162*>(&u.y);
    float2 fa = __bfloat1622float2(a);
    float2 fb = __bfloat1622float2(c);
    float* p = g_pooled + (size_t)b * DH + (lane << 2);
    asm volatile("red.global.add.v4.f32 [%0], {%1, %2, %3, %4};"
                 :: "l"(p), "f"(fa.x), "f"(fa.y), "f"(fb.x), "f"(fb.y) : "memory");
    if (lane == 0) atomicAdd(&g_cnt[b], 1);
}

// ---------------- head ----------------
__global__ void k_head(const float* __restrict__ Wout, const float* __restrict__ bout,
                       float* __restrict__ out, int G) {
    int g = blockIdx.x * blockDim.x + threadIdx.x;
    if (g >= G) return;
    float inv = 1.0f / fmaxf((float)g_cnt[g], 1.0f);
    float logit[10];
    #pragma unroll
    for (int c = 0; c < 10; ++c) logit[c] = bout[c];
    for (int k = 0; k < DH; ++k) {
        float p = g_pooled[g * DH + k] * inv;
        #pragma unroll
        for (int c = 0; c < 10; ++c) logit[c] = fmaf(p, Wout[k * 10 + c], logit[c]);
    }
    float m = logit[0];
    #pragma unroll
    for (int c = 1; c < 10; ++c) m = fmaxf(m, logit[c]);
    float s = 0.f;
    #pragma unroll
    for (int c = 0; c < 10; ++c) s += expf(logit[c] - m);
    float lse = m + logf(s);
    #pragma unroll
    for (int c = 0; c < 10; ++c) out[g * 10 + c] = logit[c] - lse;
}

extern "C" void kernel_launch(void* const* d_in, const int* in_sizes, int n_in,
                              void* d_out, int out_size) {
    const float* x    = (const float*)d_in[0];
    const float* W1   = (const float*)d_in[1];
    const float* b1   = (const float*)d_in[2];
    const float* W2   = (const float*)d_in[3];
    const float* b2   = (const float*)d_in[4];
    const float* Wout = (const float*)d_in[5];
    const float* bout = (const float*)d_in[6];
    const int*   ei   = (const int*)d_in[7];
    const int*   batch= (const int*)d_in[8];
    float* out = (float*)d_out;

    int n = in_sizes[0] / DH;
    int E = in_sizes[7] / 2;
    int G = out_size / 10;
    const int* row = ei;
    const int* col = ei + E;

    __nv_bfloat16 *Xbf, *A, *H, *W1bf, *W2bf;
    cudaGetSymbolAddress((void**)&Xbf, g_Xbf);
    cudaGetSymbolAddress((void**)&A, g_Abf);
    cudaGetSymbolAddress((void**)&H, g_Hbf);
    cudaGetSymbolAddress((void**)&W1bf, g_W1bf);
    cudaGetSymbolAddress((void**)&W2bf, g_W2bf);

    const int smemGemm = 16384 + 32768 + 32768;   // Xs + Ws + Os = 80 KB
    cudaFuncSetAttribute(k_gemm, cudaFuncAttributeMaxDynamicSharedMemorySize, smemGemm);

    // ---- preprocessing ----
    int resetTot = n > G * DH ? n : G * DH;
    k_reset<<<(resetTot + 255) / 256, 256>>>(n, G);
    k_deg_count<<<(E + 255) / 256, 256>>>(col, E);
    k_dinv<<<(n + 255) / 256, 256>>>(n);

    int nb = (n + SCAN_TILE - 1) / SCAN_TILE;
    k_scanA<<<nb, 256>>>(n);
    k_scanB<<<1, 128>>>(nb, n);
    k_scanC<<<nb, 256>>>(n);
    k_fill<<<(E + 255) / 256, 256>>>(row, col, E);

    // converts
    k_cvt<<<(n * DH / 4 + 255) / 256, 256>>>(x, Xbf, n * DH / 4);
    k_cvt<<<(DH * DH / 4 + 255) / 256, 256>>>(W1, W1bf, DH * DH / 4);
    k_cvt<<<(DH * DH / 4 + 255) / 256, 256>>>(W2, W2bf, DH * DH / 4);

    int gemmBlocks = (n + 63) / 64;
    int gatherBlocks = (n * 16 + 255) / 256;
    int poolBlocks = (n * 32 + 255) / 256;

    // Layer 1
    k_gemm<<<gemmBlocks, 256, smemGemm>>>(Xbf, W1bf, A, n);
    k_gather<<<gatherBlocks, 256>>>(A, H, b1, n);

    // Layer 2
    k_gemm<<<gemmBlocks, 256, smemGemm>>>(H, W2bf, A, n);
    k_gather<<<gatherBlocks, 256>>>(A, H, b2, n);

    // Pool + head
    k_pool<<<poolBlocks, 256>>>(H, batch, n);
    k_head<<<(G + 255) / 256, 256>>>(Wout, bout, out, G);
}

// round 7
// speedup vs baseline: 1.2250x; 1.2250x over previous
#include <cuda_runtime.h>
#include <cuda_bf16.h>
#include <mma.h>
#include <math.h>

using namespace nvcuda;

#define DH 128
#define NMAX 100000
#define EMAX 3200000
#define GMAX 512
#define SCAN_TILE 1024
#define NBMAX ((NMAX + SCAN_TILE - 1) / SCAN_TILE)   // 98
#define LDS_X 136   // padded bf16 row stride for X/W tiles
#define LDS_O 132   // padded f32 row stride for output tile

// Scratch (static device globals — no runtime allocation)
__device__ __align__(16) __nv_bfloat16 g_Xbf[NMAX * DH];
__device__ __align__(16) __nv_bfloat16 g_Abf[NMAX * DH];
__device__ __align__(16) __nv_bfloat16 g_Hbf[NMAX * DH];
__device__ __align__(16) __nv_bfloat16 g_W1bf[DH * DH];
__device__ __align__(16) __nv_bfloat16 g_W2bf[DH * DH];
__device__ float g_dinv[NMAX];
__device__ int   g_deg[NMAX];
__device__ int   g_rowptr[NMAX + 1];
__device__ int   g_cursor[NMAX];
__device__ int   g_src[EMAX];
__device__ int   g_bsum[NBMAX + 32];
__device__ int   g_boff[NBMAX + 32];
__device__ float g_pooled[GMAX * DH];
__device__ int   g_cnt[GMAX];

// ---------------- reset ----------------
__global__ void k_reset(int n, int g) {
    int idx = blockIdx.x * blockDim.x + threadIdx.x;
    if (idx < n) g_deg[idx] = 1;
    if (idx < g * DH) g_pooled[idx] = 0.0f;
    if (idx < g) g_cnt[idx] = 0;
}

__global__ void k_deg_count(const int* __restrict__ col, int E) {
    int e = blockIdx.x * blockDim.x + threadIdx.x;
    if (e < E) atomicAdd(&g_deg[col[e]], 1);
}

__global__ void k_dinv(int n) {
    int i = blockIdx.x * blockDim.x + threadIdx.x;
    if (i < n) g_dinv[i] = rsqrtf((float)g_deg[i]);
}

// ---------------- fp32 -> bf16 converter ----------------
__global__ void k_cvt(const float* __restrict__ src, __nv_bfloat16* __restrict__ dst, int total4) {
    int i = blockIdx.x * blockDim.x + threadIdx.x;
    if (i >= total4) return;
    float4 v = __ldg(reinterpret_cast<const float4*>(src) + i);
    __nv_bfloat162 p0 = __floats2bfloat162_rn(v.x, v.y);
    __nv_bfloat162 p1 = __floats2bfloat162_rn(v.z, v.w);
    uint2 o;
    o.x = *reinterpret_cast<unsigned int*>(&p0);
    o.y = *reinterpret_cast<unsigned int*>(&p1);
    reinterpret_cast<uint2*>(dst)[i] = o;
}

// ---------------- 3-phase scan ----------------
__global__ __launch_bounds__(256) void k_scanA(int n) {
    int base = blockIdx.x * SCAN_TILE;
    int tid = threadIdx.x;
    int s = 0;
    #pragma unroll
    for (int j = 0; j < 4; ++j) {
        int i = base + tid * 4 + j;
        if (i < n) s += g_deg[i] - 1;
    }
    #pragma unroll
    for (int o = 16; o; o >>= 1) s += __shfl_down_sync(~0u, s, o);
    __shared__ int ws[8];
    if ((tid & 31) == 0) ws[tid >> 5] = s;
    __syncthreads();
    if (tid < 8) {
        int v = ws[tid];
        #pragma unroll
        for (int o = 4; o; o >>= 1) v += __shfl_down_sync(0xff, v, o);
        if (tid == 0) g_bsum[blockIdx.x] = v;
    }
}

__global__ __launch_bounds__(128) void k_scanB(int nb, int n) {
    int tid = threadIdx.x;
    int s = (tid < nb) ? g_bsum[tid] : 0;
    int lane = tid & 31, wid = tid >> 5;
    int x = s;
    #pragma unroll
    for (int o = 1; o < 32; o <<= 1) {
        int y = __shfl_up_sync(~0u, x, o);
        if (lane >= o) x += y;
    }
    __shared__ int ws[4];
    if (lane == 31) ws[wid] = x;
    __syncthreads();
    if (tid < 4) {
        int y = ws[tid];
        #pragma unroll
        for (int o = 1; o < 4; o <<= 1) {
            int z = __shfl_up_sync(0xf, y, o);
            if (tid >= o) y += z;
        }
        ws[tid] = y;
    }
    __syncthreads();
    int incl = x + (wid ? ws[wid - 1] : 0);
    if (tid < nb) g_boff[tid] = incl - s;
    if (tid == 127) g_rowptr[n] = ws[3];
}

__global__ __launch_bounds__(256) void k_scanC(int n) {
    int base = blockIdx.x * SCAN_TILE;
    int tid = threadIdx.x;
    int lane = tid & 31, wid = tid >> 5;
    int v[4], s = 0;
    #pragma unroll
    for (int j = 0; j < 4; ++j) {
        int i = base + tid * 4 + j;
        v[j] = (i < n) ? g_deg[i] - 1 : 0;
        s += v[j];
    }
    int x = s;
    #pragma unroll
    for (int o = 1; o < 32; o <<= 1) {
        int y = __shfl_up_sync(~0u, x, o);
        if (lane >= o) x += y;
    }
    __shared__ int ws[8];
    if (lane == 31) ws[wid] = x;
    __syncthreads();
    if (tid < 8) {
        int y = ws[tid];
        #pragma unroll
        for (int o = 1; o < 8; o <<= 1) {
            int z = __shfl_up_sync(0xff, y, o);
            if (tid >= o) y += z;
        }
        ws[tid] = y;
    }
    __syncthreads();
    int excl = x - s + (wid ? ws[wid - 1] : 0) + g_boff[blockIdx.x];
    #pragma unroll
    for (int j = 0; j < 4; ++j) {
        int i = base + tid * 4 + j;
        if (i < n) {
            g_rowptr[i] = excl;
            g_cursor[i] = excl;
            excl += v[j];
        }
    }
}

// ---------------- fill CSR ----------------
__global__ void k_fill(const int* __restrict__ row, const int* __restrict__ col, int E) {
    int e = blockIdx.x * blockDim.x + threadIdx.x;
    if (e >= E) return;
    int r = __ldg(&row[e]);
    int c = __ldg(&col[e]);
    int pos = atomicAdd(&g_cursor[c], 1);
    g_src[pos] = r;
}

// ------- WMMA GEMM: Abf = bf16( (Xbf @ Wbf) * dinv[row] ), 64 rows/block -------
__global__ __launch_bounds__(256) void k_gemm(const __nv_bfloat16* __restrict__ X,
                                              const __nv_bfloat16* __restrict__ W,
                                              __nv_bfloat16* __restrict__ Y, int n) {
    extern __shared__ char smem[];
    __nv_bfloat16* Xs = reinterpret_cast<__nv_bfloat16*>(smem);                    // 64*136 bf16
    __nv_bfloat16* Ws = reinterpret_cast<__nv_bfloat16*>(smem + 64 * LDS_X * 2);   // 128*136 bf16
    float*         Os = reinterpret_cast<float*>(smem + (64 + 128) * LDS_X * 2);   // 64*132 f32

    int tid = threadIdx.x;
    int rowBase = blockIdx.x * 64;

    // load W: 128 rows of 128 bf16 into padded rows (16 uint4 per row)
    const uint4* Wg = reinterpret_cast<const uint4*>(W);
    #pragma unroll
    for (int i = tid; i < DH * 16; i += 256) {
        int r = i >> 4, c = i & 15;
        *reinterpret_cast<uint4*>(Ws + r * LDS_X + c * 8) = Wg[r * 16 + c];
    }
    // load X tile
    const uint4* Xg = reinterpret_cast<const uint4*>(X);
    #pragma unroll
    for (int i = tid; i < 64 * 16; i += 256) {
        int r = i >> 4, c = i & 15;
        int gr = rowBase + r;
        *reinterpret_cast<uint4*>(Xs + r * LDS_X + c * 8) =
            (gr < n) ? Xg[(size_t)gr * 16 + c] : make_uint4(0, 0, 0, 0);
    }
    __syncthreads();

    int w = tid >> 5;
    int wr = (w & 3) * 16;    // 16-row block
    int wc = (w >> 2) * 64;   // 64-col block

    wmma::fragment<wmma::accumulator, 16, 16, 16, float> fc[4];
    #pragma unroll
    for (int j = 0; j < 4; ++j) wmma::fill_fragment(fc[j], 0.0f);

    #pragma unroll
    for (int k = 0; k < 8; ++k) {
        wmma::fragment<wmma::matrix_a, 16, 16, 16, __nv_bfloat16, wmma::row_major> fa;
        wmma::load_matrix_sync(fa, Xs + wr * LDS_X + k * 16, LDS_X);
        #pragma unroll
        for (int j = 0; j < 4; ++j) {
            wmma::fragment<wmma::matrix_b, 16, 16, 16, __nv_bfloat16, wmma::row_major> fb;
            wmma::load_matrix_sync(fb, Ws + (k * 16) * LDS_X + wc + j * 16, LDS_X);
            wmma::mma_sync(fc[j], fa, fb, fc[j]);
        }
    }
    #pragma unroll
    for (int j = 0; j < 4; ++j)
        wmma::store_matrix_sync(Os + wr * LDS_O + wc + j * 16, fc[j], LDS_O, wmma::mem_row_major);
    __syncthreads();

    // epilogue: scale by dinv[row], convert to bf16, store
    int r = tid >> 2;                 // 4 threads per row
    int cb = (tid & 3) * 32;          // 32 cols per thread
    int gr = rowBase + r;
    if (gr < n) {
        float s = __ldg(&g_dinv[gr]);
        #pragma unroll
        for (int j = 0; j < 8; ++j) {
            float4 v = *reinterpret_cast<float4*>(&Os[r * LDS_O + cb + j * 4]);
            __nv_bfloat162 p0 = __floats2bfloat162_rn(v.x * s, v.y * s);
            __nv_bfloat162 p1 = __floats2bfloat162_rn(v.z * s, v.w * s);
            uint2 o;
            o.x = *reinterpret_cast<unsigned int*>(&p0);
            o.y = *reinterpret_cast<unsigned int*>(&p1);
            reinterpret_cast<uint2*>(Y)[(size_t)gr * 32 + ((cb >> 2) + j)] = o;
        }
    }
}

__device__ __forceinline__ float4 bf4_to_f4(uint2 u) {
    __nv_bfloat162 a = *reinterpret_cast<__nv_bfloat162*>(&u.x);
    __nv_bfloat162 b = *reinterpret_cast<__nv_bfloat162*>(&u.y);
    float2 fa = __bfloat1622float2(a);
    float2 fb = __bfloat1622float2(b);
    return make_float4(fa.x, fa.y, fb.x, fb.y);
}

// -------- fused gather: H[c,:] = bf16(relu( dinv[c]*(A'[c]+sum A'[r]) + b )) ---
// One full warp per destination node; lane owns 4 bf16 (8 B).
__global__ __launch_bounds__(256) void k_gather(const __nv_bfloat16* __restrict__ Ap,
                                                __nv_bfloat16* __restrict__ H,
                                                const float* __restrict__ bias,
                                                int n) {
    int lane = threadIdx.x & 31;
    int node = (blockIdx.x * blockDim.x + threadIdx.x) >> 5;
    if (node >= n) return;

    const uint2* A2 = reinterpret_cast<const uint2*>(Ap);   // 32 uint2 per row

    float4 acc = bf4_to_f4(__ldg(&A2[(size_t)node * 32 + lane]));   // self term

    int e = g_rowptr[node];
    int end = g_rowptr[node + 1];

    for (; e + 4 <= end; e += 4) {
        int r0 = __ldg(&g_src[e + 0]);
        int r1 = __ldg(&g_src[e + 1]);
        int r2 = __ldg(&g_src[e + 2]);
        int r3 = __ldg(&g_src[e + 3]);
        float4 v0 = bf4_to_f4(__ldg(&A2[(size_t)r0 * 32 + lane]));
        float4 v1 = bf4_to_f4(__ldg(&A2[(size_t)r1 * 32 + lane]));
        float4 v2 = bf4_to_f4(__ldg(&A2[(size_t)r2 * 32 + lane]));
        float4 v3 = bf4_to_f4(__ldg(&A2[(size_t)r3 * 32 + lane]));
        acc.x += v0.x + v1.x + v2.x + v3.x;
        acc.y += v0.y + v1.y + v2.y + v3.y;
        acc.z += v0.z + v1.z + v2.z + v3.z;
        acc.w += v0.w + v1.w + v2.w + v3.w;
    }
    for (; e < end; ++e) {
        int r = __ldg(&g_src[e]);
        float4 v = bf4_to_f4(__ldg(&A2[(size_t)r * 32 + lane]));
        acc.x += v.x; acc.y += v.y; acc.z += v.z; acc.w += v.w;
    }

    float dc = __ldg(&g_dinv[node]);
    float4 bb = __ldg(reinterpret_cast<const float4*>(bias) + lane);
    float o0 = fmaxf(fmaf(acc.x, dc, bb.x), 0.f);
    float o1 = fmaxf(fmaf(acc.y, dc, bb.y), 0.f);
    float o2 = fmaxf(fmaf(acc.z, dc, bb.z), 0.f);
    float o3 = fmaxf(fmaf(acc.w, dc, bb.w), 0.f);
    __nv_bfloat162 q0 = __floats2bfloat162_rn(o0, o1);
    __nv_bfloat162 q1 = __floats2bfloat162_rn(o2, o3);
    uint2 ou;
    ou.x = *reinterpret_cast<unsigned int*>(&q0);
    ou.y = *reinterpret_cast<unsigned int*>(&q1);
    reinterpret_cast<uint2*>(H)[(size_t)node * 32 + lane] = ou;
}

// ---------------- mean pool from bf16 H (fp32 atomics) ----------------
__global__ void k_pool(const __nv_bfloat16* __restrict__ H, const int* __restrict__ batch, int n) {
    int lane = threadIdx.x & 31;
    int node = (blockIdx.x * blockDim.x + threadIdx.x) >> 5;
    if (node >= n) return;
    int b = __ldg(&batch[node]);
    uint2 u = __ldg(reinterpret_cast<const uint2*>(H) + (size_t)node * 32 + lane);
    __nv_bfloat162 a = *reinterpret_cast<__nv_bfloat162*>(&u.x);
    __nv_bfloat162 c = *reinterpret_cast<__nv_bfloat162*>(&u.y);
    float2 fa = __bfloat1622float2(a);
    float2 fb = __bfloat1622float2(c);
    float* p = g_pooled + (size_t)b * DH + (lane << 2);
    asm volatile("red.global.add.v4.f32 [%0], {%1, %2, %3, %4};"
                 :: "l"(p), "f"(fa.x), "f"(fa.y), "f"(fb.x), "f"(fb.y) : "memory");
    if (lane == 0) atomicAdd(&g_cnt[b], 1);
}

// ---------------- head ----------------
__global__ void k_head(const float* __restrict__ Wout, const float* __restrict__ bout,
                       float* __restrict__ out, int G) {
    int g = blockIdx.x * blockDim.x + threadIdx.x;
    if (g >= G) return;
    float inv = 1.0f / fmaxf((float)g_cnt[g], 1.0f);
    float logit[10];
    #pragma unroll
    for (int c = 0; c < 10; ++c) logit[c] = bout[c];
    for (int k = 0; k < DH; ++k) {
        float p = g_pooled[g * DH + k] * inv;
        #pragma unroll
        for (int c = 0; c < 10; ++c) logit[c] = fmaf(p, Wout[k * 10 + c], logit[c]);
    }
    float m = logit[0];
    #pragma unroll
    for (int c = 1; c < 10; ++c) m = fmaxf(m, logit[c]);
    float s = 0.f;
    #pragma unroll
    for (int c = 0; c < 10; ++c) s += expf(logit[c] - m);
    float lse = m + logf(s);
    #pragma unroll
    for (int c = 0; c < 10; ++c) out[g * 10 + c] = logit[c] - lse;
}

extern "C" void kernel_launch(void* const* d_in, const int* in_sizes, int n_in,
                              void* d_out, int out_size) {
    const float* x    = (const float*)d_in[0];
    const float* W1   = (const float*)d_in[1];
    const float* b1   = (const float*)d_in[2];
    const float* W2   = (const float*)d_in[3];
    const float* b2   = (const float*)d_in[4];
    const float* Wout = (const float*)d_in[5];
    const float* bout = (const float*)d_in[6];
    const int*   ei   = (const int*)d_in[7];
    const int*   batch= (const int*)d_in[8];
    float* out = (float*)d_out;

    int n = in_sizes[0] / DH;
    int E = in_sizes[7] / 2;
    int G = out_size / 10;
    const int* row = ei;
    const int* col = ei + E;

    __nv_bfloat16 *Xbf, *A, *H, *W1bf, *W2bf;
    cudaGetSymbolAddress((void**)&Xbf, g_Xbf);
    cudaGetSymbolAddress((void**)&A, g_Abf);
    cudaGetSymbolAddress((void**)&H, g_Hbf);
    cudaGetSymbolAddress((void**)&W1bf, g_W1bf);
    cudaGetSymbolAddress((void**)&W2bf, g_W2bf);

    const int smemGemm = (64 + 128) * LDS_X * 2 + 64 * LDS_O * 4;   // ~86 KB
    cudaFuncSetAttribute(k_gemm, cudaFuncAttributeMaxDynamicSharedMemorySize, smemGemm);

    // ---- preprocessing ----
    int resetTot = n > G * DH ? n : G * DH;
    k_reset<<<(resetTot + 255) / 256, 256>>>(n, G);
    k_deg_count<<<(E + 255) / 256, 256>>>(col, E);
    k_dinv<<<(n + 255) / 256, 256>>>(n);

    int nb = (n + SCAN_TILE - 1) / SCAN_TILE;
    k_scanA<<<nb, 256>>>(n);
    k_scanB<<<1, 128>>>(nb, n);
    k_scanC<<<nb, 256>>>(n);
    k_fill<<<(E + 255) / 256, 256>>>(row, col, E);

    // converts
    k_cvt<<<(n * DH / 4 + 255) / 256, 256>>>(x, Xbf, n * DH / 4);
    k_cvt<<<(DH * DH / 4 + 255) / 256, 256>>>(W1, W1bf, DH * DH / 4);
    k_cvt<<<(DH * DH / 4 + 255) / 256, 256>>>(W2, W2bf, DH * DH / 4);

    int gemmBlocks = (n + 63) / 64;
    int warpBlocks = (n * 32 + 255) / 256;

    // Layer 1
    k_gemm<<<gemmBlocks, 256, smemGemm>>>(Xbf, W1bf, A, n);
    k_gather<<<warpBlocks, 256>>>(A, H, b1, n);

    // Layer 2
    k_gemm<<<gemmBlocks, 256, smemGemm>>>(H, W2bf, A, n);
    k_gather<<<warpBlocks, 256>>>(A, H, b2, n);

    // Pool + head
    k_pool<<<warpBlocks, 256>>>(H, batch, n);
    k_head<<<(G + 255) / 256, 256>>>(Wout, bout, out, G);
}